// round 2
// baseline (speedup 1.0000x reference)
#include <cuda_runtime.h>
#include <cuda_bf16.h>

// NnHalfKA: NNUE-style sparse feature transform + tiny head, fully fused.
//
// Inputs (metadata order):
//  0 values    float32 [NNZ]
//  1 W_ft      float32 [49152, 512]
//  2 ft_b      float32 [512]
//  3 W_fft     float32 [768, 512]
//  4 fft_b     float32 [512]
//  5 W_out     float32 [1, 1024]
//  6 out_b     float32 [1]
//  7 batch_ids int32   [NNZ]   (sorted ascending)
//  8 stm_feat  int32   [NNZ]
//  9 nstm_feat int32   [NNZ]
// 10 size      int32   [1]     (== out_size, unused on device)
//
// Output: float32 [B] = sigmoid( clip(acc,0,1) . W_out + out_b )

#define FT_DIM   512
#define F_VIRT   768
#define NTHREADS 128

__device__ __forceinline__ float clip01(float x) {
    return fminf(fmaxf(x, 0.0f), 1.0f);
}

__global__ __launch_bounds__(NTHREADS)
void nnue_fused_kernel(const float* __restrict__ values,
                       const float* __restrict__ W_ft,
                       const float* __restrict__ ft_b,
                       const float* __restrict__ W_fft,
                       const float* __restrict__ fft_b,
                       const float* __restrict__ W_out,
                       const float* __restrict__ out_b,
                       const int*   __restrict__ batch_ids,
                       const int*   __restrict__ stm_feat,
                       const int*   __restrict__ nstm_feat,
                       float*       __restrict__ out,
                       int nnz)
{
    const int b = blockIdx.x;
    const int t = threadIdx.x;

    __shared__ int s_range[2];
    __shared__ float s_red[NTHREADS / 32];

    // Segment bounds via two binary searches on sorted batch_ids.
    if (t == 0) {
        int lo = 0, hi = nnz;
        while (lo < hi) { int m = (lo + hi) >> 1; if (__ldg(batch_ids + m) <  b) lo = m + 1; else hi = m; }
        s_range[0] = lo;
        hi = nnz;
        while (lo < hi) { int m = (lo + hi) >> 1; if (__ldg(batch_ids + m) <= b) lo = m + 1; else hi = m; }
        s_range[1] = lo;
    }
    __syncthreads();
    const int start = s_range[0];
    const int end   = s_range[1];

    const int c = t * 4;  // this thread's 4 columns

    float4 accs = make_float4(0.f, 0.f, 0.f, 0.f);
    float4 accn = make_float4(0.f, 0.f, 0.f, 0.f);

    for (int i = start; i < end; ++i) {
        const int   fs = __ldg(stm_feat + i);
        const int   fn = __ldg(nstm_feat + i);
        const float v  = __ldg(values + i);

        const float4 as = __ldg((const float4*)(W_ft  + (size_t)fs * FT_DIM + c));
        const float4 bs = __ldg((const float4*)(W_fft + (size_t)(fs % F_VIRT) * FT_DIM + c));
        const float4 an = __ldg((const float4*)(W_ft  + (size_t)fn * FT_DIM + c));
        const float4 bn = __ldg((const float4*)(W_fft + (size_t)(fn % F_VIRT) * FT_DIM + c));

        accs.x = fmaf(as.x + bs.x, v, accs.x);
        accs.y = fmaf(as.y + bs.y, v, accs.y);
        accs.z = fmaf(as.z + bs.z, v, accs.z);
        accs.w = fmaf(as.w + bs.w, v, accs.w);

        accn.x = fmaf(an.x + bn.x, v, accn.x);
        accn.y = fmaf(an.y + bn.y, v, accn.y);
        accn.z = fmaf(an.z + bn.z, v, accn.z);
        accn.w = fmaf(an.w + bn.w, v, accn.w);
    }

    // Bias, clip, and dot with W_out fragments.
    const float4 fb = __ldg((const float4*)(ft_b  + c));
    const float4 gb = __ldg((const float4*)(fft_b + c));
    const float4 ws = __ldg((const float4*)(W_out + c));            // stm half
    const float4 wn = __ldg((const float4*)(W_out + FT_DIM + c));   // nstm half

    float p = 0.f;
    p = fmaf(clip01(accs.x + fb.x + gb.x), ws.x, p);
    p = fmaf(clip01(accs.y + fb.y + gb.y), ws.y, p);
    p = fmaf(clip01(accs.z + fb.z + gb.z), ws.z, p);
    p = fmaf(clip01(accs.w + fb.w + gb.w), ws.w, p);
    p = fmaf(clip01(accn.x + fb.x + gb.x), wn.x, p);
    p = fmaf(clip01(accn.y + fb.y + gb.y), wn.y, p);
    p = fmaf(clip01(accn.z + fb.z + gb.z), wn.z, p);
    p = fmaf(clip01(accn.w + fb.w + gb.w), wn.w, p);

    // Block reduction: warp shuffle then smem across 4 warps.
    #pragma unroll
    for (int off = 16; off > 0; off >>= 1)
        p += __shfl_down_sync(0xffffffffu, p, off);
    if ((t & 31) == 0) s_red[t >> 5] = p;
    __syncthreads();

    if (t == 0) {
        float tot = s_red[0] + s_red[1] + s_red[2] + s_red[3] + __ldg(out_b);
        out[b] = 1.0f / (1.0f + expf(-tot));
    }
}

extern "C" void kernel_launch(void* const* d_in, const int* in_sizes, int n_in,
                              void* d_out, int out_size) {
    const float* values    = (const float*)d_in[0];
    const float* W_ft      = (const float*)d_in[1];
    const float* ft_b      = (const float*)d_in[2];
    const float* W_fft     = (const float*)d_in[3];
    const float* fft_b     = (const float*)d_in[4];
    const float* W_out     = (const float*)d_in[5];
    const float* out_b     = (const float*)d_in[6];
    const int*   batch_ids = (const int*)d_in[7];
    const int*   stm_feat  = (const int*)d_in[8];
    const int*   nstm_feat = (const int*)d_in[9];
    float*       out       = (float*)d_out;

    const int nnz = in_sizes[0];
    const int B   = out_size;  // 8192 rows, one CTA each

    nnue_fused_kernel<<<B, NTHREADS>>>(values, W_ft, ft_b, W_fft, fft_b,
                                       W_out, out_b, batch_ids,
                                       stm_feat, nstm_feat, out, nnz);
}

// round 5
// speedup vs baseline: 1.1720x; 1.1720x over previous
#include <cuda_runtime.h>
#include <cuda_bf16.h>

// NnHalfKA fused NNUE, round 2:
//   Kernel 1: W_comb[f] = bf16(W_ft[f] + W_fft[f % 768])  (rebuilt every launch)
//   Kernel 2: per-batch gather-sum from W_comb (bf16 rows, fp32 accum),
//             bias + clip + dot(W_out) + sigmoid, fully fused.
//
// Rationale: R1 was L1TEX-wavefront bound (63%) moving 2.15 GB of gather
// traffic. Fusing the two tables and storing bf16 cuts L1 bytes 4x.

#define F_FULL   49152
#define F_VIRT   768
#define FT_DIM   512
#define NTHREADS 128

// 49152 * 512 bf16 = 50.3 MB static device scratch (allowed; no allocation).
__device__ __nv_bfloat16 g_wcomb[(size_t)F_FULL * FT_DIM];

__device__ __forceinline__ float clip01(float x) {
    return fminf(fmaxf(x, 0.0f), 1.0f);
}

// ---------------------------------------------------------------------------
// Kernel 1: build combined bf16 table. One thread per float4 (4 columns).
// Total float4 elements: F_FULL * FT_DIM / 4 = 6,291,456  (24576 blocks x 256)
// ---------------------------------------------------------------------------
__global__ __launch_bounds__(256)
void build_comb_kernel(const float* __restrict__ W_ft,
                       const float* __restrict__ W_fft)
{
    const int idx = blockIdx.x * 256 + threadIdx.x;   // float4 index
    const int f   = idx >> 7;                         // 128 float4 per row
    const int c4  = idx & 127;

    const float4 a = __ldg((const float4*)W_ft + idx);
    const float4 b = __ldg((const float4*)W_fft + (f % F_VIRT) * 128 + c4);

    __nv_bfloat162 lo = __floats2bfloat162_rn(a.x + b.x, a.y + b.y);
    __nv_bfloat162 hi = __floats2bfloat162_rn(a.z + b.z, a.w + b.w);

    uint2 p;
    p.x = *reinterpret_cast<unsigned*>(&lo);
    p.y = *reinterpret_cast<unsigned*>(&hi);
    reinterpret_cast<uint2*>(g_wcomb)[idx] = p;
}

// ---------------------------------------------------------------------------
// Kernel 2: one CTA per batch row. Thread t owns columns [4t, 4t+4).
// Per nnz: two 8-byte gathers (stm/nstm row slices) from the bf16 table.
// ---------------------------------------------------------------------------
__global__ __launch_bounds__(NTHREADS)
void nnue_gather_kernel(const float* __restrict__ values,
                        const float* __restrict__ ft_b,
                        const float* __restrict__ fft_b,
                        const float* __restrict__ W_out,
                        const float* __restrict__ out_b,
                        const int*   __restrict__ batch_ids,
                        const int*   __restrict__ stm_feat,
                        const int*   __restrict__ nstm_feat,
                        float*       __restrict__ out,
                        int nnz)
{
    const int b = blockIdx.x;
    const int t = threadIdx.x;

    __shared__ int s_range[2];
    __shared__ float s_red[NTHREADS / 32];

    // Segment bounds via binary search on sorted batch_ids.
    if (t == 0) {
        int lo = 0, hi = nnz;
        while (lo < hi) { int m = (lo + hi) >> 1; if (__ldg(batch_ids + m) <  b) lo = m + 1; else hi = m; }
        s_range[0] = lo;
        hi = nnz;
        while (lo < hi) { int m = (lo + hi) >> 1; if (__ldg(batch_ids + m) <= b) lo = m + 1; else hi = m; }
        s_range[1] = lo;
    }
    __syncthreads();
    const int start = s_range[0];
    const int end   = s_range[1];

    const uint2* __restrict__ Wc = reinterpret_cast<const uint2*>(g_wcomb);
    // Row stride in uint2 units: 512 bf16 = 128 uint2.

    float4 accs = make_float4(0.f, 0.f, 0.f, 0.f);
    float4 accn = make_float4(0.f, 0.f, 0.f, 0.f);

    #pragma unroll 4
    for (int i = start; i < end; ++i) {
        const int   fs = __ldg(stm_feat + i);
        const int   fn = __ldg(nstm_feat + i);
        const float v  = __ldg(values + i);

        const uint2 rs = __ldg(Wc + (size_t)fs * 128 + t);
        const uint2 rn = __ldg(Wc + (size_t)fn * 128 + t);

        const float2 s01 = __bfloat1622float2(*reinterpret_cast<const __nv_bfloat162*>(&rs.x));
        const float2 s23 = __bfloat1622float2(*reinterpret_cast<const __nv_bfloat162*>(&rs.y));
        const float2 n01 = __bfloat1622float2(*reinterpret_cast<const __nv_bfloat162*>(&rn.x));
        const float2 n23 = __bfloat1622float2(*reinterpret_cast<const __nv_bfloat162*>(&rn.y));

        accs.x = fmaf(s01.x, v, accs.x);
        accs.y = fmaf(s01.y, v, accs.y);
        accs.z = fmaf(s23.x, v, accs.z);
        accs.w = fmaf(s23.y, v, accs.w);

        accn.x = fmaf(n01.x, v, accn.x);
        accn.y = fmaf(n01.y, v, accn.y);
        accn.z = fmaf(n23.x, v, accn.z);
        accn.w = fmaf(n23.y, v, accn.w);
    }

    // Bias, clip, dot with W_out fragments (all fp32, exact).
    const int c = t * 4;
    const float4 fb = __ldg((const float4*)(ft_b  + c));
    const float4 gb = __ldg((const float4*)(fft_b + c));
    const float4 ws = __ldg((const float4*)(W_out + c));            // stm half
    const float4 wn = __ldg((const float4*)(W_out + FT_DIM + c));   // nstm half

    float p = 0.f;
    p = fmaf(clip01(accs.x + fb.x + gb.x), ws.x, p);
    p = fmaf(clip01(accs.y + fb.y + gb.y), ws.y, p);
    p = fmaf(clip01(accs.z + fb.z + gb.z), ws.z, p);
    p = fmaf(clip01(accs.w + fb.w + gb.w), ws.w, p);
    p = fmaf(clip01(accn.x + fb.x + gb.x), wn.x, p);
    p = fmaf(clip01(accn.y + fb.y + gb.y), wn.y, p);
    p = fmaf(clip01(accn.z + fb.z + gb.z), wn.z, p);
    p = fmaf(clip01(accn.w + fb.w + gb.w), wn.w, p);

    #pragma unroll
    for (int off = 16; off > 0; off >>= 1)
        p += __shfl_down_sync(0xffffffffu, p, off);
    if ((t & 31) == 0) s_red[t >> 5] = p;
    __syncthreads();

    if (t == 0) {
        float tot = s_red[0] + s_red[1] + s_red[2] + s_red[3] + __ldg(out_b);
        out[b] = 1.0f / (1.0f + expf(-tot));
    }
}

extern "C" void kernel_launch(void* const* d_in, const int* in_sizes, int n_in,
                              void* d_out, int out_size) {
    const float* values    = (const float*)d_in[0];
    const float* W_ft      = (const float*)d_in[1];
    const float* ft_b      = (const float*)d_in[2];
    const float* W_fft     = (const float*)d_in[3];
    const float* fft_b     = (const float*)d_in[4];
    const float* W_out     = (const float*)d_in[5];
    const float* out_b     = (const float*)d_in[6];
    const int*   batch_ids = (const int*)d_in[7];
    const int*   stm_feat  = (const int*)d_in[8];
    const int*   nstm_feat = (const int*)d_in[9];
    float*       out       = (float*)d_out;

    const int nnz = in_sizes[0];
    const int B   = out_size;

    // Rebuild combined table every launch (deterministic, no caching).
    const int total_f4 = (F_FULL * FT_DIM) / 4;          // 6,291,456
    build_comb_kernel<<<total_f4 / 256, 256>>>(W_ft, W_fft);

    nnue_gather_kernel<<<B, NTHREADS>>>(values, ft_b, fft_b,
                                        W_out, out_b, batch_ids,
                                        stm_feat, nstm_feat, out, nnz);
}